// round 6
// baseline (speedup 1.0000x reference)
#include <cuda_runtime.h>
#include <cuda_fp16.h>
#include <math.h>
#include <stdint.h>

// Glm4vMoeTextTopkRouter: tensor-core router GEMM (baseline mma.sync, fp16 split precision,
// scaled residuals, periodic software flush) + fused sigmoid + bias top-8 + normalize.
// R6: 512 threads (16 warps, 4/SMSP) for latency hiding; warp tile m16n32; merged cor bank.

#define HD 4096
#define NE 128
#define TOPK 8
#define BM 64                // tokens per CTA
#define KC 64                // k per chunk
#define NCH (HD / KC)        // 64
#define NT 512               // 16 warps

#define OFF_BIAS  0
#define OFF_STAGE 512
#define A_MAT 8192           // 64 rows x 128B
#define B_MAT 16384          // 128 rows x 128B
#define STG (2 * A_MAT + 2 * B_MAT)       // 49152: A_hi | A_lo | B_hi | B_lo
#define SMEM_TOTAL (OFF_STAGE + 2 * STG)  // 98816

#define LO_SCALE 2048.0f
#define LO_INV   (1.0f / 2048.0f)

#define SW128(o) ((uint32_t)(o) ^ ((((uint32_t)(o)) >> 3) & 0x70))

__device__ __forceinline__ uint32_t smem_u32(const void* p) {
    uint32_t a;
    asm("{ .reg .u64 t; cvta.to.shared.u64 t, %1; cvt.u32.u64 %0, t; }" : "=r"(a) : "l"(p));
    return a;
}

__device__ __forceinline__ void ldsm_x4(uint32_t addr, uint32_t& r0, uint32_t& r1,
                                        uint32_t& r2, uint32_t& r3) {
    asm volatile("ldmatrix.sync.aligned.m8n8.x4.shared.b16 {%0,%1,%2,%3}, [%4];"
                 : "=r"(r0), "=r"(r1), "=r"(r2), "=r"(r3) : "r"(addr));
}

__device__ __forceinline__ void mma16816(float* c, const uint32_t* a, uint32_t b0, uint32_t b1) {
    asm volatile("mma.sync.aligned.m16n8k16.row.col.f32.f16.f16.f32 "
                 "{%0,%1,%2,%3}, {%4,%5,%6,%7}, {%8,%9}, {%0,%1,%2,%3};"
                 : "+f"(c[0]), "+f"(c[1]), "+f"(c[2]), "+f"(c[3])
                 : "r"(a[0]), "r"(a[1]), "r"(a[2]), "r"(a[3]), "r"(b0), "r"(b1));
}

__device__ __forceinline__ uint32_t h2u(half2 h) { return *reinterpret_cast<uint32_t*>(&h); }

__device__ __forceinline__ void store_split(char* hi_p, char* lo_p, float4 v) {
    half2 h0 = __floats2half2_rn(v.x, v.y);
    half2 h1 = __floats2half2_rn(v.z, v.w);
    float2 f0 = __half22float2(h0);
    float2 f1 = __half22float2(h1);
    half2 l0 = __floats2half2_rn((v.x - f0.x) * LO_SCALE, (v.y - f0.y) * LO_SCALE);
    half2 l1 = __floats2half2_rn((v.z - f1.x) * LO_SCALE, (v.w - f1.y) * LO_SCALE);
    *(uint2*)hi_p = make_uint2(h2u(h0), h2u(h1));
    *(uint2*)lo_p = make_uint2(h2u(l0), h2u(l1));
}

// verified ldmatrix address maps (128B pitch, SW128)
__device__ __forceinline__ uint32_t a_addr(uint32_t base, int l, int mb, int kb) {
    int row = mb + (l & 7) + ((l >> 3) & 1) * 8;
    int colb = (kb + ((l >> 4) << 3)) * 2;
    return base + SW128(row * 128 + colb);
}
__device__ __forceinline__ uint32_t b_addr(uint32_t base, int l, int nb, int kb) {
    int row = nb + (l & 7) + ((l >> 4) << 3);
    int colb = (kb + (((l >> 3) & 1) << 3)) * 2;
    return base + SW128(row * 128 + colb);
}

__global__ __launch_bounds__(NT, 1)
void router_mma_kernel(const float* __restrict__ hidden,
                       const float* __restrict__ weight,
                       const float* __restrict__ bias,
                       float* __restrict__ out, int T)
{
    extern __shared__ char smem[];
    const uint32_t sbase = smem_u32(smem);
    const int tid = threadIdx.x;
    const int wid = tid >> 5, lid = tid & 31;
    const int m0 = blockIdx.x * BM;

    if (tid < NE) ((float*)(smem + OFF_BIAS))[tid] = bias[tid];

    const int arow = tid >> 4;   // 0..31
    const int c4   = tid & 15;   // float4 within KC=64
    const float* aBase = hidden + (size_t)(m0 + arow) * HD + c4 * 4;
    const float* bBase = weight + (size_t)arow * HD + c4 * 4;

    // warp grid 4m x 4n; warp tile m16 x n32
    const int mb = (wid >> 2) * 16;
    const int nb = (wid & 3) * 32;

    float acc[4][4], cor[4][4], sum[4][4];
#pragma unroll
    for (int j = 0; j < 4; j++)
#pragma unroll
        for (int q = 0; q < 4; q++) { acc[j][q] = 0.0f; cor[j][q] = 0.0f; sum[j][q] = 0.0f; }

    float4 va[2], vb[4];
#pragma unroll
    for (int i = 0; i < 2; i++) va[i] = *(const float4*)(aBase + (size_t)(i * 32) * HD);
#pragma unroll
    for (int i = 0; i < 4; i++) vb[i] = *(const float4*)(bBase + (size_t)(i * 32) * HD);

    for (int c = 0; c < NCH; ++c) {
        char* stg = smem + OFF_STAGE + (c & 1) * STG;
#pragma unroll
        for (int i = 0; i < 2; i++) {   // A: 64 rows
            uint32_t off = SW128((uint32_t)((i * 32 + arow) * 128 + c4 * 8));
            store_split(stg + off, stg + A_MAT + off, va[i]);
        }
#pragma unroll
        for (int i = 0; i < 4; i++) {   // B: 128 rows
            uint32_t off = SW128((uint32_t)((i * 32 + arow) * 128 + c4 * 8));
            store_split(stg + 2 * A_MAT + off, stg + 2 * A_MAT + B_MAT + off, vb[i]);
        }
        if (c + 1 < NCH) {
            const float* ap = aBase + (size_t)(c + 1) * KC;
            const float* bp = bBase + (size_t)(c + 1) * KC;
#pragma unroll
            for (int i = 0; i < 2; i++) va[i] = *(const float4*)(ap + (size_t)(i * 32) * HD);
#pragma unroll
            for (int i = 0; i < 4; i++) vb[i] = *(const float4*)(bp + (size_t)(i * 32) * HD);
        }
        __syncthreads();   // orders STS->LDSM; buffer-reuse safety via barrier chain

        const uint32_t sA_hi = sbase + OFF_STAGE + (c & 1) * STG;
        const uint32_t sA_lo = sA_hi + A_MAT;
        const uint32_t sB_hi = sA_hi + 2 * A_MAT;
        const uint32_t sB_lo = sB_hi + B_MAT;

#pragma unroll
        for (int ks = 0; ks < 4; ks++) {
            const int kb = ks * 16;
            uint32_t ah[4], al[4];
            ldsm_x4(a_addr(sA_hi, lid, mb, kb), ah[0], ah[1], ah[2], ah[3]);
            ldsm_x4(a_addr(sA_lo, lid, mb, kb), al[0], al[1], al[2], al[3]);

            uint32_t bh[2][4], bl[2][4];
#pragma unroll
            for (int ng = 0; ng < 2; ng++) {
                ldsm_x4(b_addr(sB_hi, lid, nb + ng * 16, kb),
                        bh[ng][0], bh[ng][1], bh[ng][2], bh[ng][3]);
                ldsm_x4(b_addr(sB_lo, lid, nb + ng * 16, kb),
                        bl[ng][0], bl[ng][1], bl[ng][2], bl[ng][3]);
            }
            // HH
#pragma unroll
            for (int ng = 0; ng < 2; ng++) {
                mma16816(acc[ng * 2 + 0], ah, bh[ng][0], bh[ng][1]);
                mma16816(acc[ng * 2 + 1], ah, bh[ng][2], bh[ng][3]);
            }
            // HL then LH into the same cor bank, spaced >= 4 HMMA apart per register
#pragma unroll
            for (int ng = 0; ng < 2; ng++) {
                mma16816(cor[ng * 2 + 0], ah, bl[ng][0], bl[ng][1]);
                mma16816(cor[ng * 2 + 1], ah, bl[ng][2], bl[ng][3]);
            }
#pragma unroll
            for (int ng = 0; ng < 2; ng++) {
                mma16816(cor[ng * 2 + 0], al, bh[ng][0], bh[ng][1]);
                mma16816(cor[ng * 2 + 1], al, bh[ng][2], bh[ng][3]);
            }
        }

        // flush TC accumulators into software fp32 sum every 4 chunks
        if ((c & 3) == 3) {
#pragma unroll
            for (int j = 0; j < 4; j++)
#pragma unroll
                for (int q = 0; q < 4; q++) {
                    float s = sum[j][q] + acc[j][q];
                    s = fmaf(cor[j][q], LO_INV, s);
                    sum[j][q] = s;
                    acc[j][q] = 0.0f; cor[j][q] = 0.0f;
                }
        }
    }

    __syncthreads();   // all LDSM reads done before scoreboard overlays stage smem

    // epilogue: sigmoid(sum) -> scoreboard [row][129]
    float* sc = (float*)(smem + OFF_STAGE);
    {
        const int r0 = lid >> 2;
        const int cc = (lid & 3) * 2;
#pragma unroll
        for (int j = 0; j < 4; j++) {
            const int col = nb + j * 8 + cc;
#pragma unroll
            for (int q = 0; q < 4; q++) {
                const int row = mb + r0 + (q >> 1) * 8;
                sc[row * 129 + col + (q & 1)] = 1.0f / (1.0f + expf(-sum[j][q]));
            }
        }
    }
    __syncthreads();

    // top-8 per token (threads 0..63); strict '>' => lowest-index ties like lax.top_k
    if (tid < BM) {
        const int gtok = m0 + tid;
        float* row = sc + tid * 129;
        const float* sb = (const float*)(smem + OFF_BIAS);
        float w[TOPK]; int idx[TOPK]; float ssum = 0.0f;
#pragma unroll
        for (int p = 0; p < TOPK; p++) {
            float mx = -1e30f; int mi = 0;
#pragma unroll 16
            for (int e = 0; e < NE; e++) {
                float v = row[e] + sb[e];
                if (v > mx) { mx = v; mi = e; }
            }
            idx[p] = mi;
            w[p] = row[mi];
            row[mi] = -3e30f;
            ssum += w[p];
        }
        const float inv = 1.0f / (ssum + 1e-20f);
        float* oi = out + (size_t)gtok * TOPK;
        float* ow = out + (size_t)T * TOPK + (size_t)gtok * TOPK;
#pragma unroll
        for (int p = 0; p < TOPK; p++) {
            oi[p] = (float)idx[p];
            ow[p] = w[p] * inv;
        }
    }
}

extern "C" void kernel_launch(void* const* d_in, const int* in_sizes, int n_in,
                              void* d_out, int out_size)
{
    const float* hidden = (const float*)d_in[0];
    const float* weight = (const float*)d_in[1];
    const float* bias   = (const float*)d_in[2];
    const int T = in_sizes[0] / HD;   // 32768

    cudaFuncSetAttribute(router_mma_kernel,
                         cudaFuncAttributeMaxDynamicSharedMemorySize, SMEM_TOTAL);
    router_mma_kernel<<<T / BM, NT, SMEM_TOTAL>>>(hidden, weight, bias, (float*)d_out, T);
}